// round 13
// baseline (speedup 1.0000x reference)
#include <cuda_runtime.h>
#include <cuda_bf16.h>
#include <math.h>

#define NN 50000
#define EE 512000
#define BG 64

// ---------------- scratch ----------------
__device__ float g_h[NN * 64];
__device__ float g_q[NN * 256];          // q'(scaled)[0:128) skip[128:192) u[192:208) qb[208:210)
__device__ unsigned int g_kvh[NN * 128]; // bf16x2: k[0:64) v[64:128)
__device__ float g_outp[NN * 64];
__device__ float g_Wall[2 * 64 * 512];
__device__ float g_ball[2 * 512];
__device__ uint2 g_WB[2 * 64 * 4 * 32];  // B fragments
__device__ float g_Wf[2 * 1024];
__device__ float g_bf[2 * 128];
__device__ float g_stats[128];
__device__ float g_bn[128];
__device__ float g_pool[BG * 64];
__device__ float g_gden[BG];
// CSR
__device__ int g_deg[NN];
__device__ int g_cur[NN];
__device__ int g_off[NN + 1];
__device__ int g_bsum[256];
__device__ int g_boff[256];
__device__ int g_srcs[EE];
__device__ float g_eatp[EE * 8];

typedef unsigned long long ull;

// ---------------- helpers ----------------
__device__ __forceinline__ ull pack2(float x, float y) {
    ull d;
    asm("mov.b64 %0, {%1, %2};" : "=l"(d) : "r"(__float_as_uint(x)), "r"(__float_as_uint(y)));
    return d;
}
__device__ __forceinline__ unsigned int bfpack(float x, float y) {
    unsigned int d;
    asm("cvt.rn.bf16x2.f32 %0, %1, %2;" : "=r"(d) : "f"(y), "f"(x));
    return d;
}
__device__ __forceinline__ float bflo(unsigned int w) { return __uint_as_float(w << 16); }
__device__ __forceinline__ float bfhi(unsigned int w) { return __uint_as_float(w & 0xffff0000u); }
__device__ __forceinline__ unsigned int smem_u32(const void* p) {
    unsigned int a;
    asm("{ .reg .u64 t; cvta.to.shared.u64 t, %1; cvt.u32.u64 %0, t; }" : "=r"(a) : "l"(p));
    return a;
}

// ---------------- merged: node encoder + setup1 ----------------
__global__ void __launch_bounds__(256) enc_setup1_kernel(
    const float* __restrict__ x, const float* __restrict__ node_W, const float* __restrict__ node_b,
    const float* __restrict__ Wq, const float* __restrict__ bq,
    const float* __restrict__ Wk, const float* __restrict__ bk,
    const float* __restrict__ Wv, const float* __restrict__ bv,
    const float* __restrict__ Wskip, const float* __restrict__ bskip,
    const float* __restrict__ edge_W, const float* __restrict__ edge_b,
    const float* __restrict__ We, const float* __restrict__ be,
    int n, int nbe) {
    int tid = threadIdx.x;
    if (blockIdx.x >= (unsigned)nbe) {
        const int TOT = 65536 + 1024 + 2048 + 256;
        int bid2 = blockIdx.x - nbe;
        for (int idx = bid2 * 256 + tid; idx < TOT; idx += 128 * 256) {
            if (idx < 65536) {
                int c = idx & 511, j = (idx >> 9) & 63, i = idx >> 15;
                float v = 0.f;
                if (c < 128)      v = 0.125f * Wq[(i * 64 + j) * 128 + c];
                else if (c < 256) v = Wk[(i * 64 + j) * 128 + (c - 128)];
                else if (c < 384) v = Wv[(i * 64 + j) * 128 + (c - 256)];
                else if (c < 448) v = Wskip[(i * 64 + j) * 64 + (c - 384)];
                g_Wall[idx] = v;
            } else if (idx < 66560) {
                int t = idx - 65536; int c = t & 511, i = t >> 9;
                float v = 0.f;
                if (c < 128)      v = 0.125f * bq[i * 128 + c];
                else if (c < 256) v = bk[i * 128 + (c - 128)];
                else if (c < 384) v = bv[i * 128 + (c - 256)];
                else if (c < 448) v = bskip[i * 64 + (c - 384)];
                g_ball[t] = v;
            } else if (idx < 68608) {
                int t = idx - 66560; int i = t >> 10; int r = t & 1023;
                int j = r >> 7; int c = r & 127;
                float acc = 0.f;
                #pragma unroll 8
                for (int m = 0; m < 64; m++) acc += edge_W[j * 64 + m] * We[(i * 64 + m) * 128 + c];
                g_Wf[t] = acc;
            } else {
                int t = idx - 68608; int i = t >> 7; int c = t & 127;
                float acc = be[i * 128 + c];
                #pragma unroll 8
                for (int m = 0; m < 64; m++) acc += edge_b[m] * We[(i * 64 + m) * 128 + c];
                g_bf[i * 128 + c] = acc;
            }
        }
        return;
    }
    __shared__ float Ws[16 * 64];
    __shared__ float bs[64];
    for (int i = tid; i < 1024; i += 256) Ws[i] = node_W[i];
    if (tid < 64) bs[tid] = node_b[tid];
    __syncthreads();
    int idx = blockIdx.x * 256 + tid;
    if (idx >= n * 64) return;
    int nn = idx >> 6, c = idx & 63;
    const float* xr = x + nn * 16;
    float acc = bs[c];
    #pragma unroll
    for (int j = 0; j < 16; j++) acc += xr[j] * Ws[j * 64 + c];
    g_h[idx] = acc;
}

// ---------------- setup2: u / qb columns ----------------
__global__ void setup2_kernel() {
    int idx = blockIdx.x * blockDim.x + threadIdx.x;
    if (idx < 2 * 64 * 18) {
        int i = idx / (64 * 18); int r = idx % (64 * 18);
        int m = r / 18; int col = r % 18;
        const float* Wf = g_Wf + i * 1024;
        const float* bf = g_bf + i * 128;
        const float* Wrow = g_Wall + i * 64 * 512 + m * 512;
        float acc = 0.f;
        if (col < 16) {
            int h = col >> 3, j = col & 7;
            #pragma unroll 8
            for (int c = 0; c < 64; c++) acc += Wrow[h * 64 + c] * Wf[j * 128 + h * 64 + c];
            g_Wall[i * 64 * 512 + m * 512 + 448 + col] = acc;
        } else {
            int h = col - 16;
            #pragma unroll 8
            for (int c = 0; c < 64; c++) acc += Wrow[h * 64 + c] * bf[h * 64 + c];
            g_Wall[i * 64 * 512 + m * 512 + 464 + h] = acc;
        }
    } else if (idx < 2 * 64 * 18 + 2 * 18) {
        int t = idx - 2 * 64 * 18; int i = t / 18; int col = t % 18;
        const float* Wf = g_Wf + i * 1024;
        const float* bf = g_bf + i * 128;
        const float* Brow = g_ball + i * 512;
        float acc = 0.f;
        if (col < 16) {
            int h = col >> 3, j = col & 7;
            #pragma unroll 8
            for (int c = 0; c < 64; c++) acc += Brow[h * 64 + c] * Wf[j * 128 + h * 64 + c];
            g_ball[i * 512 + 448 + col] = acc;
        } else {
            int h = col - 16;
            #pragma unroll 8
            for (int c = 0; c < 64; c++) acc += Brow[h * 64 + c] * bf[h * 64 + c];
            g_ball[i * 512 + 464 + h] = acc;
        }
    }
}

// ---------------- setup3: pack weights into mma B-fragment layout ----------------
__global__ void setup3_kernel() {
    int idx = blockIdx.x * blockDim.x + threadIdx.x;
    if (idx >= 2 * 64 * 4 * 32) return;
    int lane = idx & 31;
    int ks = (idx >> 5) & 3;
    int nt = (idx >> 7) & 63;
    int layer = idx >> 13;
    int col = nt * 8 + (lane >> 2);
    int k0 = ks * 16 + (lane & 3) * 2;
    const float* W = g_Wall + layer * 64 * 512;
    unsigned int b0 = bfpack(W[k0 * 512 + col], W[(k0 + 1) * 512 + col]);
    unsigned int b1 = bfpack(W[(k0 + 8) * 512 + col], W[(k0 + 9) * 512 + col]);
    g_WB[idx] = make_uint2(b0, b1);
}

// ---------------- CSR build ----------------
__global__ void csr_hist_kernel(const int* __restrict__ edst, int E) {
    int e = blockIdx.x * blockDim.x + threadIdx.x;
    if (e < E) atomicAdd(&g_deg[edst[e]], 1);
}
__global__ void scan1_kernel(int n) {
    __shared__ int sd[256];
    int i = blockIdx.x * 256 + threadIdx.x;
    int v = (i < n) ? g_deg[i] : 0;
    sd[threadIdx.x] = v;
    __syncthreads();
    for (int off = 128; off > 0; off >>= 1) {
        if (threadIdx.x < off) sd[threadIdx.x] += sd[threadIdx.x + off];
        __syncthreads();
    }
    if (threadIdx.x == 0) g_bsum[blockIdx.x] = sd[0];
}
__global__ void scan2_kernel(int nb, int n, int E) {
    __shared__ int sd[256];
    int tid = threadIdx.x;
    int v = (tid < nb) ? g_bsum[tid] : 0;
    sd[tid] = v;
    __syncthreads();
    for (int off = 1; off < 256; off <<= 1) {
        int t = (tid >= off) ? sd[tid - off] : 0;
        __syncthreads();
        sd[tid] += t;
        __syncthreads();
    }
    if (tid < nb) g_boff[tid] = sd[tid] - v;
    if (tid == 0) g_off[n] = E;
}
__global__ void scan3_kernel(int n) {
    __shared__ int sd[256];
    int tid = threadIdx.x;
    int i = blockIdx.x * 256 + tid;
    int v = (i < n) ? g_deg[i] : 0;
    sd[tid] = v;
    __syncthreads();
    for (int off = 1; off < 256; off <<= 1) {
        int t = (tid >= off) ? sd[tid - off] : 0;
        __syncthreads();
        sd[tid] += t;
        __syncthreads();
    }
    if (i < n) g_off[i] = g_boff[blockIdx.x] + sd[tid] - v;
}
__global__ void csr_scatter_kernel(const float* __restrict__ eat,
                                   const int* __restrict__ esrc, const int* __restrict__ edst,
                                   int E) {
    int e = blockIdx.x * blockDim.x + threadIdx.x;
    if (e >= E) return;
    int d = edst[e];
    int pos = atomicAdd(&g_cur[d], 1);
    int slot = g_off[d] + pos;
    g_srcs[slot] = esrc[e];
    float4 a0 = *(const float4*)(eat + (size_t)e * 8);
    float4 a1 = *(const float4*)(eat + (size_t)e * 8 + 4);
    *(float4*)(g_eatp + (size_t)slot * 8) = a0;
    *(float4*)(g_eatp + (size_t)slot * 8 + 4) = a1;
}

// ---------------- qkvs GEMM via mma.sync bf16; two-pass epilogue ----------------
__global__ void __launch_bounds__(256, 4) qkvs_kernel(int layer, int n, int fuse,
                                                      const float* __restrict__ gamma,
                                                      const float* __restrict__ beta) {
    __shared__ __align__(16) unsigned short hsb[32 * 72];
    int tid = threadIdx.x;
    int n0 = blockIdx.x * 32;

    for (int i = tid; i < 32 * 64; i += 256) {
        int r = i >> 6, c = i & 63;
        int nn = n0 + r;
        float v = 0.f;
        if (nn < n) {
            if (fuse) {
                float o = g_outp[nn * 64 + c];
                float hv = g_h[nn * 64 + c];
                float bnv = __ldg(&gamma[c]) * (o - g_bn[c]) * g_bn[64 + c] + __ldg(&beta[c]);
                bnv = (bnv > 0.f) ? bnv : 0.01f * bnv;
                v = hv + bnv;
                g_h[nn * 64 + c] = v;
            } else {
                v = g_h[nn * 64 + c];
            }
        }
        __nv_bfloat16 b = __float2bfloat16(v);
        hsb[r * 72 + c] = *(unsigned short*)&b;
    }
    __syncthreads();

    int lane = tid & 31;
    int warp = tid >> 5;
    int mt = warp >> 2;
    int cgp = warp & 3;

    unsigned int afr[4][4];
    unsigned int abase = smem_u32(hsb) +
        ((mt * 16 + (lane & 15)) * 72 + ((lane >> 4) * 8)) * 2;
    #pragma unroll
    for (int ks = 0; ks < 4; ks++) {
        asm volatile("ldmatrix.sync.aligned.m8n8.x4.shared.b16 {%0,%1,%2,%3}, [%4];"
                     : "=r"(afr[ks][0]), "=r"(afr[ks][1]), "=r"(afr[ks][2]), "=r"(afr[ks][3])
                     : "r"(abase + ks * 32));
    }

    const uint2* WB = g_WB + ((size_t)layer * 64 + cgp * 16) * 4 * 32;
    const float* ball = g_ball + layer * 512;
    int r0 = n0 + mt * 16 + (lane >> 2);
    int colb = cgp * 128 + (lane & 3) * 2;

    #pragma unroll
    for (int pass = 0; pass < 2; pass++) {
        float c[8][4];
        #pragma unroll
        for (int nt = 0; nt < 8; nt++)
            #pragma unroll
            for (int k = 0; k < 4; k++) c[nt][k] = 0.f;

        #pragma unroll
        for (int ks = 0; ks < 4; ks++) {
            #pragma unroll
            for (int nt = 0; nt < 8; nt++) {
                uint2 b = WB[((pass * 8 + nt) * 4 + ks) * 32 + lane];
                asm volatile(
                    "mma.sync.aligned.m16n8k16.row.col.f32.bf16.bf16.f32 "
                    "{%0,%1,%2,%3},{%4,%5,%6,%7},{%8,%9},{%0,%1,%2,%3};"
                    : "+f"(c[nt][0]), "+f"(c[nt][1]), "+f"(c[nt][2]), "+f"(c[nt][3])
                    : "r"(afr[ks][0]), "r"(afr[ks][1]), "r"(afr[ks][2]), "r"(afr[ks][3]),
                      "r"(b.x), "r"(b.y));
            }
        }

        #pragma unroll
        for (int nt = 0; nt < 8; nt++) {
            int col = colb + (pass * 8 + nt) * 8;
            float2 bb = *(const float2*)&ball[col];
            #pragma unroll
            for (int half = 0; half < 2; half++) {
                int row = r0 + half * 8;
                if (row >= n) continue;
                float v0 = c[nt][half * 2 + 0] + bb.x;
                float v1 = c[nt][half * 2 + 1] + bb.y;
                if (cgp == 0) {
                    *(float2*)&g_q[(size_t)row * 256 + col] = make_float2(v0, v1);
                } else if (cgp == 3) {
                    *(float2*)&g_q[(size_t)row * 256 + 128 + (col - 384)] = make_float2(v0, v1);
                } else if (cgp == 1) {
                    g_kvh[row * 128 + ((col - 128) >> 1)] = bfpack(v0, v1);
                } else {
                    g_kvh[row * 128 + 64 + ((col - 256) >> 1)] = bfpack(v0, v1);
                }
            }
        }
    }
}

// ---------------- CSR gather: one node per warp, 2 edges split across half-warps ----------------
// lane = eh*16 + hl*8 + j8; eh = edge slot (0/1), hl = head, j8 = 0..7.
// lane owns dims (lane&15)*8 .. +8 of the 128-dim k/v rows.
__global__ void __launch_bounds__(256) gather_kernel(int layer, int n) {
    __shared__ float Wfs[1024];
    __shared__ float bfs[128];
    __shared__ float ss[128];
    int tid = threadIdx.x;
    {
        const float* Wf = g_Wf + layer * 1024;
        const float* bf = g_bf + layer * 128;
        for (int i = tid; i < 1024; i += 256) Wfs[i] = Wf[i];
        if (tid < 128) { bfs[tid] = bf[tid]; ss[tid] = 0.f; }
    }
    __syncthreads();

    int lane = tid & 31;
    int warp = tid >> 5;
    int eh = lane >> 4;        // edge slot within pair
    int d16 = lane & 15;       // dim-group: owns dims d16*8..+8
    int hl = d16 >> 3;         // head of owned dims
    int j8 = lane & 7;         // edge-attr index

    float bsum[8], bsq[8];
    #pragma unroll
    for (int w = 0; w < 8; w++) { bsum[w] = 0.f; bsq[w] = 0.f; }

    int nwarps = gridDim.x * (blockDim.x >> 5);
    for (int nn = blockIdx.x * (blockDim.x >> 5) + warp; nn < n; nn += nwarps) {
        const float* bq_ = g_q + (size_t)nn * 256;
        float4 qa = *(const float4*)(bq_ + d16 * 8);
        float4 qb4 = *(const float4*)(bq_ + d16 * 8 + 4);
        float u = bq_[192 + hl * 8 + j8];
        float qbias = bq_[208 + hl];
        int off0 = g_off[nn], off1 = g_off[nn + 1];

        float vacc[8];
        #pragma unroll
        for (int w = 0; w < 8; w++) vacc[w] = 0.f;
        float den = 0.f, t = 0.f;

        for (int idx = off0; idx < off1; idx += 2) {
            int ei = idx + eh;
            bool ev = ei < off1;
            int ii = ev ? ei : idx;
            int s = g_srcs[ii];
            float ea = g_eatp[(size_t)ii * 8 + j8];
            const unsigned int* kb = g_kvh + (size_t)s * 128 + d16 * 4;
            uint4 kk = *(const uint4*)kb;
            uint4 vv = *(const uint4*)(kb + 64);
            float p = qa.x * bflo(kk.x) + qa.y * bfhi(kk.x)
                    + qa.z * bflo(kk.y) + qa.w * bfhi(kk.y)
                    + qb4.x * bflo(kk.z) + qb4.y * bfhi(kk.z)
                    + qb4.z * bflo(kk.w) + qb4.w * bfhi(kk.w)
                    + ea * u;
            // reduce over 8-lane (edge, head) group
            p += __shfl_xor_sync(0xffffffffu, p, 4);
            p += __shfl_xor_sync(0xffffffffu, p, 2);
            p += __shfl_xor_sync(0xffffffffu, p, 1);
            float a = ev ? __expf(p + qbias) : 0.f;
            vacc[0] += a * bflo(vv.x);
            vacc[1] += a * bfhi(vv.x);
            vacc[2] += a * bflo(vv.y);
            vacc[3] += a * bfhi(vv.y);
            vacc[4] += a * bflo(vv.z);
            vacc[5] += a * bfhi(vv.z);
            vacc[6] += a * bflo(vv.w);
            vacc[7] += a * bfhi(vv.w);
            den += a;
            t += a * ea;
        }

        // combine the two edge slots (xor 16)
        #pragma unroll
        for (int w = 0; w < 8; w++) vacc[w] += __shfl_xor_sync(0xffffffffu, vacc[w], 16);
        den += __shfl_xor_sync(0xffffffffu, den, 16);
        t += __shfl_xor_sync(0xffffffffu, t, 16);

        // lanes 0..15: full sums for dims d16*8..+8; den/t per head hl
        // ep[w] for dim c = d16*8+w: den*bf[c] + sum_j t[hl][j]*Wf[j][c]
        float ep[8];
        #pragma unroll
        for (int w = 0; w < 8; w++) ep[w] = den * bfs[d16 * 8 + w];
        #pragma unroll
        for (int j = 0; j < 8; j++) {
            float tj = __shfl_sync(0xffffffffu, t, (lane & 8) + j);
            float4 wA = *(float4*)&Wfs[j * 128 + d16 * 8];
            float4 wB = *(float4*)&Wfs[j * 128 + d16 * 8 + 4];
            ep[0] += tj * wA.x; ep[1] += tj * wA.y;
            ep[2] += tj * wA.z; ep[3] += tj * wA.w;
            ep[4] += tj * wB.x; ep[5] += tj * wB.y;
            ep[6] += tj * wB.z; ep[7] += tj * wB.w;
        }
        float inv = (den > 0.f) ? 0.5f / den : 0.f;
        float agg[8];
        #pragma unroll
        for (int w = 0; w < 8; w++) agg[w] = (vacc[w] + ep[w]) * inv;
        // cross-head combine (xor 8): lanes 0..7 get out dims (lane)*8..+8
        #pragma unroll
        for (int w = 0; w < 8; w++) agg[w] += __shfl_xor_sync(0xffffffffu, agg[w], 8);

        if (lane < 8) {
            const float* sk = bq_ + 128 + lane * 8;
            float4 skA = *(const float4*)sk;
            float4 skB = *(const float4*)(sk + 4);
            float o0 = agg[0] + skA.x, o1 = agg[1] + skA.y;
            float o2 = agg[2] + skA.z, o3 = agg[3] + skA.w;
            float o4 = agg[4] + skB.x, o5 = agg[5] + skB.y;
            float o6 = agg[6] + skB.z, o7 = agg[7] + skB.w;
            float* op = &g_outp[(size_t)nn * 64 + lane * 8];
            *(float4*)op = make_float4(o0, o1, o2, o3);
            *(float4*)(op + 4) = make_float4(o4, o5, o6, o7);
            bsum[0] += o0; bsq[0] += o0 * o0;
            bsum[1] += o1; bsq[1] += o1 * o1;
            bsum[2] += o2; bsq[2] += o2 * o2;
            bsum[3] += o3; bsq[3] += o3 * o3;
            bsum[4] += o4; bsq[4] += o4 * o4;
            bsum[5] += o5; bsq[5] += o5 * o5;
            bsum[6] += o6; bsq[6] += o6 * o6;
            bsum[7] += o7; bsq[7] += o7 * o7;
        }
    }

    if (lane < 8) {
        #pragma unroll
        for (int w = 0; w < 8; w++) {
            atomicAdd(&ss[lane * 8 + w], bsum[w]);
            atomicAdd(&ss[64 + lane * 8 + w], bsq[w]);
        }
    }
    __syncthreads();
    if (tid < 128) atomicAdd(&g_stats[tid], ss[tid]);
}

// ---------------- BN params ----------------
__global__ void bnparam_kernel(float invn, int zero_pool) {
    int t = threadIdx.x;  // 64
    float s = g_stats[t], sq = g_stats[64 + t];
    float mu = s * invn;
    float var = sq * invn - mu * mu;
    g_bn[t] = mu;
    g_bn[64 + t] = rsqrtf(var + 1e-5f);
    g_stats[t] = 0.f;
    g_stats[64 + t] = 0.f;
    if (zero_pool) {
        for (int i = t; i < BG * 64; i += 64) g_pool[i] = 0.f;
        if (t < BG) g_gden[t] = 0.f;
    }
}

// ---------------- pooling with fused BN-apply + leaky_relu + residual ----------------
__global__ void __launch_bounds__(256) pool_kernel(const int* __restrict__ batch,
                                                   const float* __restrict__ gate_W,
                                                   const float* __restrict__ gate_b,
                                                   const float* __restrict__ gamma,
                                                   const float* __restrict__ beta, int n) {
    for (int i = blockIdx.x * blockDim.x + threadIdx.x; i < n;
         i += gridDim.x * blockDim.x) {
        g_deg[i] = 0;
        g_cur[i] = 0;
    }

    int lane = threadIdx.x & 31;
    int w = (blockIdx.x * 256 + threadIdx.x) >> 5;
    int n0 = w * 64;
    if (n0 >= n) return;
    int n1 = min(n0 + 64, n);

    int c0 = lane * 2;
    float2 gw = ((const float2*)gate_W)[lane];
    float gb = gate_b[0];
    float2 ga = make_float2(__ldg(&gamma[c0]), __ldg(&gamma[c0 + 1]));
    float2 be = make_float2(__ldg(&beta[c0]), __ldg(&beta[c0 + 1]));
    float2 mu = make_float2(g_bn[c0], g_bn[c0 + 1]);
    float2 rs = make_float2(g_bn[64 + c0], g_bn[64 + c0 + 1]);

    int cur = -1;
    float ax = 0.f, ay = 0.f, ws = 0.f;
    for (int nn = n0; nn < n1; nn++) {
        float2 hv = ((const float2*)g_h)[nn * 32 + lane];
        float2 ov = ((const float2*)g_outp)[nn * 32 + lane];
        float v0 = ga.x * (ov.x - mu.x) * rs.x + be.x;
        float v1 = ga.y * (ov.y - mu.y) * rs.y + be.y;
        v0 = (v0 > 0.f) ? v0 : 0.01f * v0;
        v1 = (v1 > 0.f) ? v1 : 0.01f * v1;
        float h0 = hv.x + v0;
        float h1 = hv.y + v1;
        float p = h0 * gw.x + h1 * gw.y;
        p += __shfl_xor_sync(0xffffffffu, p, 16);
        p += __shfl_xor_sync(0xffffffffu, p, 8);
        p += __shfl_xor_sync(0xffffffffu, p, 4);
        p += __shfl_xor_sync(0xffffffffu, p, 2);
        p += __shfl_xor_sync(0xffffffffu, p, 1);
        float wt = __expf(p + gb);
        int b = batch[nn];
        if (b != cur) {
            if (cur >= 0) {
                atomicAdd(&g_pool[cur * 64 + c0], ax);
                atomicAdd(&g_pool[cur * 64 + c0 + 1], ay);
                if (lane == 0) atomicAdd(&g_gden[cur], ws);
            }
            cur = b; ax = ay = ws = 0.f;
        }
        ax += wt * h0;
        ay += wt * h1;
        ws += wt;
    }
    if (cur >= 0) {
        atomicAdd(&g_pool[cur * 64 + c0], ax);
        atomicAdd(&g_pool[cur * 64 + c0 + 1], ay);
        if (lane == 0) atomicAdd(&g_gden[cur], ws);
    }
}

// ---------------- final readout ----------------
__global__ void final_kernel(const float* __restrict__ out_W,
                             const float* __restrict__ out_b, float* __restrict__ out) {
    int lane = threadIdx.x & 31;
    int b = (blockIdx.x * blockDim.x + threadIdx.x) >> 5;
    if (b >= BG) return;
    float2 ow = ((const float2*)out_W)[lane];
    float2 p = ((const float2*)g_pool)[b * 32 + lane];
    float gd = g_gden[b];
    float inv = (gd > 0.f) ? 1.f / gd : 0.f;
    float v = (p.x * ow.x + p.y * ow.y) * inv;
    v += __shfl_xor_sync(0xffffffffu, v, 16);
    v += __shfl_xor_sync(0xffffffffu, v, 8);
    v += __shfl_xor_sync(0xffffffffu, v, 4);
    v += __shfl_xor_sync(0xffffffffu, v, 2);
    v += __shfl_xor_sync(0xffffffffu, v, 1);
    if (lane == 0) out[b] = 1.f / (1.f + __expf(-(v + out_b[0])));
}

// ---------------- launch ----------------
extern "C" void kernel_launch(void* const* d_in, const int* in_sizes, int n_in,
                              void* d_out, int out_size) {
    const float* x      = (const float*)d_in[0];
    const float* eat    = (const float*)d_in[1];
    const int*   esrc   = (const int*)d_in[2];
    const int*   edst   = (const int*)d_in[3];
    const int*   batch  = (const int*)d_in[4];
    const float* node_W = (const float*)d_in[5];
    const float* node_b = (const float*)d_in[6];
    const float* edge_W = (const float*)d_in[7];
    const float* edge_b = (const float*)d_in[8];
    const float* Wq     = (const float*)d_in[9];
    const float* bq     = (const float*)d_in[10];
    const float* Wk     = (const float*)d_in[11];
    const float* bk     = (const float*)d_in[12];
    const float* Wv     = (const float*)d_in[13];
    const float* bv     = (const float*)d_in[14];
    const float* We     = (const float*)d_in[15];
    const float* be     = (const float*)d_in[16];
    const float* Wskip  = (const float*)d_in[17];
    const float* bskip  = (const float*)d_in[18];
    const float* gamma  = (const float*)d_in[19];
    const float* beta   = (const float*)d_in[20];
    const float* gate_W = (const float*)d_in[21];
    const float* gate_b = (const float*)d_in[22];
    const float* out_W  = (const float*)d_in[23];
    const float* out_b  = (const float*)d_in[24];
    float* out = (float*)d_out;

    int n = in_sizes[0] / 16;
    int E = in_sizes[1] / 8;
    int nb = (n + 255) / 256;
    int nbe = (n * 64 + 255) / 256;
    int qkvs_blocks = (n + 31) / 32;
    float invn = 1.0f / (float)n;

    enc_setup1_kernel<<<nbe + 128, 256>>>(x, node_W, node_b,
                                          Wq, bq, Wk, bk, Wv, bv, Wskip, bskip,
                                          edge_W, edge_b, We, be, n, nbe);     // 0
    setup2_kernel<<<(2 * 64 * 18 + 2 * 18 + 255) / 256, 256>>>();              // 1
    setup3_kernel<<<64, 256>>>();                                              // 2
    qkvs_kernel<<<qkvs_blocks, 256>>>(0, n, 0, gamma, beta);                   // 3 (profiled)

    csr_hist_kernel<<<(E + 255) / 256, 256>>>(edst, E);                        // 4
    scan1_kernel<<<nb, 256>>>(n);                                              // 5
    scan2_kernel<<<1, 256>>>(nb, n, E);                                        // 6
    scan3_kernel<<<nb, 256>>>(n);                                              // 7
    csr_scatter_kernel<<<(E + 255) / 256, 256>>>(eat, esrc, edst, E);          // 8

    gather_kernel<<<1480, 256>>>(0, n);                                        // 9
    bnparam_kernel<<<1, 64>>>(invn, 0);                                        // 10
    qkvs_kernel<<<qkvs_blocks, 256>>>(1, n, 1, gamma, beta);                   // 11
    gather_kernel<<<1480, 256>>>(1, n);                                        // 12
    bnparam_kernel<<<1, 64>>>(invn, 1);                                        // 13

    int pool_blocks = ((n + 63) / 64 + 7) / 8;
    pool_kernel<<<pool_blocks, 256>>>(batch, gate_W, gate_b,
                                      gamma + 64, beta + 64, n);               // 14
    final_kernel<<<(BG * 64 + 63) / 64, 64>>>(out_W, out_b, out);              // 15
}

// round 14
// speedup vs baseline: 1.2736x; 1.2736x over previous
#include <cuda_runtime.h>
#include <cuda_bf16.h>
#include <math.h>

#define NN 50000
#define EE 512000
#define BG 64

// ---------------- scratch ----------------
__device__ float g_h[NN * 64];
__device__ float g_q[NN * 256];          // q'(scaled)[0:128) skip[128:192) u[192:208) qb[208:210)
__device__ unsigned int g_kvh[NN * 128]; // interleaved bf16x2 words: even=k pair, odd=v pair
__device__ float g_outp[NN * 64];
__device__ float g_Wall[2 * 64 * 512];
__device__ float g_ball[2 * 512];
__device__ uint2 g_WB[2 * 64 * 4 * 32];  // mma B fragments
__device__ float g_Wf[2 * 1024];
__device__ float g_bf[2 * 128];
__device__ float g_stats[128];
__device__ float g_bn[128];
__device__ float g_pool[BG * 64];
__device__ float g_gden[BG];
// CSR
__device__ int g_deg[NN];
__device__ int g_cur[NN];
__device__ int g_off[NN + 1];
__device__ int g_bsum[256];
__device__ int g_boff[256];
__device__ int g_srcs[EE];
__device__ float g_eatp[EE * 8];

typedef unsigned long long ull;

// ---------------- helpers ----------------
__device__ __forceinline__ ull pack2(float x, float y) {
    ull d;
    asm("mov.b64 %0, {%1, %2};" : "=l"(d) : "r"(__float_as_uint(x)), "r"(__float_as_uint(y)));
    return d;
}
__device__ __forceinline__ ull add2(ull a, ull b) {
    ull d;
    asm("add.rn.f32x2 %0, %1, %2;" : "=l"(d) : "l"(a), "l"(b));
    return d;
}
__device__ __forceinline__ float2 unpack2(ull v) {
    unsigned int lo, hi;
    asm("mov.b64 {%0, %1}, %2;" : "=r"(lo), "=r"(hi) : "l"(v));
    return make_float2(__uint_as_float(lo), __uint_as_float(hi));
}
__device__ __forceinline__ unsigned int bfpack(float x, float y) {
    unsigned int d;
    asm("cvt.rn.bf16x2.f32 %0, %1, %2;" : "=r"(d) : "f"(y), "f"(x));
    return d;
}
__device__ __forceinline__ float bflo(unsigned int w) { return __uint_as_float(w << 16); }
__device__ __forceinline__ float bfhi(unsigned int w) { return __uint_as_float(w & 0xffff0000u); }
__device__ __forceinline__ unsigned int smem_u32(const void* p) {
    unsigned int a;
    asm("{ .reg .u64 t; cvta.to.shared.u64 t, %1; cvt.u32.u64 %0, t; }" : "=r"(a) : "l"(p));
    return a;
}

// ---------------- L0: node encoder + setup1 + csr_hist (all independent) ----------------
__global__ void __launch_bounds__(256) enc_setup1_hist_kernel(
    const float* __restrict__ x, const float* __restrict__ node_W, const float* __restrict__ node_b,
    const float* __restrict__ Wq, const float* __restrict__ bq,
    const float* __restrict__ Wk, const float* __restrict__ bk,
    const float* __restrict__ Wv, const float* __restrict__ bv,
    const float* __restrict__ Wskip, const float* __restrict__ bskip,
    const float* __restrict__ edge_W, const float* __restrict__ edge_b,
    const float* __restrict__ We, const float* __restrict__ be,
    const int* __restrict__ edst,
    int n, int E, int nbe, int nbh) {
    int tid = threadIdx.x;
    if (blockIdx.x >= (unsigned)(nbe + 128)) {
        // ---- csr hist ----
        int e = (blockIdx.x - nbe - 128) * 256 + tid;
        if (e < E) atomicAdd(&g_deg[edst[e]], 1);
        return;
    }
    if (blockIdx.x >= (unsigned)nbe) {
        // ---- setup1 ----
        const int TOT = 65536 + 1024 + 2048 + 256;
        int bid2 = blockIdx.x - nbe;
        for (int idx = bid2 * 256 + tid; idx < TOT; idx += 128 * 256) {
            if (idx < 65536) {
                int c = idx & 511, j = (idx >> 9) & 63, i = idx >> 15;
                float v = 0.f;
                if (c < 128)      v = 0.125f * Wq[(i * 64 + j) * 128 + c];
                else if (c < 256) v = Wk[(i * 64 + j) * 128 + (c - 128)];
                else if (c < 384) v = Wv[(i * 64 + j) * 128 + (c - 256)];
                else if (c < 448) v = Wskip[(i * 64 + j) * 64 + (c - 384)];
                g_Wall[idx] = v;
            } else if (idx < 66560) {
                int t = idx - 65536; int c = t & 511, i = t >> 9;
                float v = 0.f;
                if (c < 128)      v = 0.125f * bq[i * 128 + c];
                else if (c < 256) v = bk[i * 128 + (c - 128)];
                else if (c < 384) v = bv[i * 128 + (c - 256)];
                else if (c < 448) v = bskip[i * 64 + (c - 384)];
                g_ball[t] = v;
            } else if (idx < 68608) {
                int t = idx - 66560; int i = t >> 10; int r = t & 1023;
                int j = r >> 7; int c = r & 127;
                float acc = 0.f;
                #pragma unroll 8
                for (int m = 0; m < 64; m++) acc += edge_W[j * 64 + m] * We[(i * 64 + m) * 128 + c];
                g_Wf[t] = acc;
            } else {
                int t = idx - 68608; int i = t >> 7; int c = t & 127;
                float acc = be[i * 128 + c];
                #pragma unroll 8
                for (int m = 0; m < 64; m++) acc += edge_b[m] * We[(i * 64 + m) * 128 + c];
                g_bf[i * 128 + c] = acc;
            }
        }
        return;
    }
    // ---- node encoder ----
    __shared__ float Ws[16 * 64];
    __shared__ float bs[64];
    for (int i = tid; i < 1024; i += 256) Ws[i] = node_W[i];
    if (tid < 64) bs[tid] = node_b[tid];
    __syncthreads();
    int idx = blockIdx.x * 256 + tid;
    if (idx >= n * 64) return;
    int nn = idx >> 6, c = idx & 63;
    const float* xr = x + nn * 16;
    float acc = bs[c];
    #pragma unroll
    for (int j = 0; j < 16; j++) acc += xr[j] * Ws[j * 64 + c];
    g_h[idx] = acc;
}

// ---------------- L1: setup2 (blocks 0..9) + scan1 (rest) ----------------
__global__ void setup2_scan1_kernel(int n, int ns2b) {
    int tid = threadIdx.x;
    if (blockIdx.x >= (unsigned)ns2b) {
        // ---- scan1 ----
        __shared__ int sd[256];
        int bid2 = blockIdx.x - ns2b;
        int i = bid2 * 256 + tid;
        int v = (i < n) ? g_deg[i] : 0;
        sd[tid] = v;
        __syncthreads();
        for (int off = 128; off > 0; off >>= 1) {
            if (tid < off) sd[tid] += sd[tid + off];
            __syncthreads();
        }
        if (tid == 0) g_bsum[bid2] = sd[0];
        return;
    }
    int idx = blockIdx.x * 256 + tid;
    if (idx < 2 * 64 * 18) {
        int i = idx / (64 * 18); int r = idx % (64 * 18);
        int m = r / 18; int col = r % 18;
        const float* Wf = g_Wf + i * 1024;
        const float* bf = g_bf + i * 128;
        const float* Wrow = g_Wall + i * 64 * 512 + m * 512;
        float acc = 0.f;
        if (col < 16) {
            int h = col >> 3, j = col & 7;
            #pragma unroll 8
            for (int c = 0; c < 64; c++) acc += Wrow[h * 64 + c] * Wf[j * 128 + h * 64 + c];
            g_Wall[i * 64 * 512 + m * 512 + 448 + col] = acc;
        } else {
            int h = col - 16;
            #pragma unroll 8
            for (int c = 0; c < 64; c++) acc += Wrow[h * 64 + c] * bf[h * 64 + c];
            g_Wall[i * 64 * 512 + m * 512 + 464 + h] = acc;
        }
    } else if (idx < 2 * 64 * 18 + 2 * 18) {
        int t = idx - 2 * 64 * 18; int i = t / 18; int col = t % 18;
        const float* Wf = g_Wf + i * 1024;
        const float* bf = g_bf + i * 128;
        const float* Brow = g_ball + i * 512;
        float acc = 0.f;
        if (col < 16) {
            int h = col >> 3, j = col & 7;
            #pragma unroll 8
            for (int c = 0; c < 64; c++) acc += Brow[h * 64 + c] * Wf[j * 128 + h * 64 + c];
            g_ball[i * 512 + 448 + col] = acc;
        } else {
            int h = col - 16;
            #pragma unroll 8
            for (int c = 0; c < 64; c++) acc += Brow[h * 64 + c] * bf[h * 64 + c];
            g_ball[i * 512 + 464 + h] = acc;
        }
    }
}

// ---------------- L2: setup3 (blocks 0..63) + scan2 (block 64) ----------------
__global__ void setup3_scan2_kernel(int nb, int n, int E) {
    int tid = threadIdx.x;
    if (blockIdx.x == 64) {
        __shared__ int sd[256];
        int v = (tid < nb) ? g_bsum[tid] : 0;
        sd[tid] = v;
        __syncthreads();
        for (int off = 1; off < 256; off <<= 1) {
            int t = (tid >= off) ? sd[tid - off] : 0;
            __syncthreads();
            sd[tid] += t;
            __syncthreads();
        }
        if (tid < nb) g_boff[tid] = sd[tid] - v;
        if (tid == 0) g_off[n] = E;
        return;
    }
    int idx = blockIdx.x * 256 + tid;
    if (idx >= 2 * 64 * 4 * 32) return;
    int lane = idx & 31;
    int ks = (idx >> 5) & 3;
    int nt = (idx >> 7) & 63;
    int layer = idx >> 13;
    int col = nt * 8 + (lane >> 2);
    int k0 = ks * 16 + (lane & 3) * 2;
    const float* W = g_Wall + layer * 64 * 512;
    unsigned int b0 = bfpack(W[k0 * 512 + col], W[(k0 + 1) * 512 + col]);
    unsigned int b1 = bfpack(W[(k0 + 8) * 512 + col], W[(k0 + 9) * 512 + col]);
    g_WB[idx] = make_uint2(b0, b1);
}

__global__ void scan3_kernel(int n) {
    __shared__ int sd[256];
    int tid = threadIdx.x;
    int i = blockIdx.x * 256 + tid;
    int v = (i < n) ? g_deg[i] : 0;
    sd[tid] = v;
    __syncthreads();
    for (int off = 1; off < 256; off <<= 1) {
        int t = (tid >= off) ? sd[tid - off] : 0;
        __syncthreads();
        sd[tid] += t;
        __syncthreads();
    }
    if (i < n) g_off[i] = g_boff[blockIdx.x] + sd[tid] - v;
}
__global__ void csr_scatter_kernel(const float* __restrict__ eat,
                                   const int* __restrict__ esrc, const int* __restrict__ edst,
                                   int E) {
    int e = blockIdx.x * blockDim.x + threadIdx.x;
    if (e >= E) return;
    int d = edst[e];
    int pos = atomicAdd(&g_cur[d], 1);
    int slot = g_off[d] + pos;
    g_srcs[slot] = esrc[e];
    float4 a0 = *(const float4*)(eat + (size_t)e * 8);
    float4 a1 = *(const float4*)(eat + (size_t)e * 8 + 4);
    *(float4*)(g_eatp + (size_t)slot * 8) = a0;
    *(float4*)(g_eatp + (size_t)slot * 8 + 4) = a1;
}

// ---------------- qkvs GEMM via mma.sync bf16; two-pass epilogue, interleaved kv out ----------------
__global__ void __launch_bounds__(256, 4) qkvs_kernel(int layer, int n, int fuse,
                                                      const float* __restrict__ gamma,
                                                      const float* __restrict__ beta) {
    __shared__ __align__(16) unsigned short hsb[32 * 72];
    int tid = threadIdx.x;
    int n0 = blockIdx.x * 32;

    for (int i = tid; i < 32 * 64; i += 256) {
        int r = i >> 6, c = i & 63;
        int nn = n0 + r;
        float v = 0.f;
        if (nn < n) {
            if (fuse) {
                float o = g_outp[nn * 64 + c];
                float hv = g_h[nn * 64 + c];
                float bnv = __ldg(&gamma[c]) * (o - g_bn[c]) * g_bn[64 + c] + __ldg(&beta[c]);
                bnv = (bnv > 0.f) ? bnv : 0.01f * bnv;
                v = hv + bnv;
                g_h[nn * 64 + c] = v;
            } else {
                v = g_h[nn * 64 + c];
            }
        }
        __nv_bfloat16 b = __float2bfloat16(v);
        hsb[r * 72 + c] = *(unsigned short*)&b;
    }
    __syncthreads();

    int lane = tid & 31;
    int warp = tid >> 5;
    int mt = warp >> 2;
    int cgp = warp & 3;

    unsigned int afr[4][4];
    unsigned int abase = smem_u32(hsb) +
        ((mt * 16 + (lane & 15)) * 72 + ((lane >> 4) * 8)) * 2;
    #pragma unroll
    for (int ks = 0; ks < 4; ks++) {
        asm volatile("ldmatrix.sync.aligned.m8n8.x4.shared.b16 {%0,%1,%2,%3}, [%4];"
                     : "=r"(afr[ks][0]), "=r"(afr[ks][1]), "=r"(afr[ks][2]), "=r"(afr[ks][3])
                     : "r"(abase + ks * 32));
    }

    const uint2* WB = g_WB + ((size_t)layer * 64 + cgp * 16) * 4 * 32;
    const float* ball = g_ball + layer * 512;
    int r0 = n0 + mt * 16 + (lane >> 2);
    int colb = cgp * 128 + (lane & 3) * 2;

    #pragma unroll
    for (int pass = 0; pass < 2; pass++) {
        float c[8][4];
        #pragma unroll
        for (int nt = 0; nt < 8; nt++)
            #pragma unroll
            for (int k = 0; k < 4; k++) c[nt][k] = 0.f;

        #pragma unroll
        for (int ks = 0; ks < 4; ks++) {
            #pragma unroll
            for (int nt = 0; nt < 8; nt++) {
                uint2 b = WB[((pass * 8 + nt) * 4 + ks) * 32 + lane];
                asm volatile(
                    "mma.sync.aligned.m16n8k16.row.col.f32.bf16.bf16.f32 "
                    "{%0,%1,%2,%3},{%4,%5,%6,%7},{%8,%9},{%0,%1,%2,%3};"
                    : "+f"(c[nt][0]), "+f"(c[nt][1]), "+f"(c[nt][2]), "+f"(c[nt][3])
                    : "r"(afr[ks][0]), "r"(afr[ks][1]), "r"(afr[ks][2]), "r"(afr[ks][3]),
                      "r"(b.x), "r"(b.y));
            }
        }

        #pragma unroll
        for (int nt = 0; nt < 8; nt++) {
            int col = colb + (pass * 8 + nt) * 8;
            float2 bb = *(const float2*)&ball[col];
            #pragma unroll
            for (int half = 0; half < 2; half++) {
                int row = r0 + half * 8;
                if (row >= n) continue;
                float v0 = c[nt][half * 2 + 0] + bb.x;
                float v1 = c[nt][half * 2 + 1] + bb.y;
                if (cgp == 0) {
                    *(float2*)&g_q[(size_t)row * 256 + col] = make_float2(v0, v1);
                } else if (cgp == 3) {
                    *(float2*)&g_q[(size_t)row * 256 + 128 + (col - 384)] = make_float2(v0, v1);
                } else if (cgp == 1) {
                    // k pair for dims (col-128, col-127) -> even word slot
                    g_kvh[row * 128 + (col - 128)] = bfpack(v0, v1);
                } else {
                    // v pair for dims (col-256, col-255) -> odd word slot
                    g_kvh[row * 128 + (col - 256) + 1] = bfpack(v0, v1);
                }
            }
        }
    }
}

// ---------------- CSR gather (R8 shape; interleaved kv = one LDG.128 per edge) ----------------
__global__ void __launch_bounds__(256) gather_kernel(int layer, int n) {
    __shared__ float Wfs[1024];
    __shared__ float bfs[128];
    __shared__ float ss[128];
    int tid = threadIdx.x;
    {
        const float* Wf = g_Wf + layer * 1024;
        const float* bf = g_bf + layer * 128;
        for (int i = tid; i < 1024; i += 256) Wfs[i] = Wf[i];
        if (tid < 128) { bfs[tid] = bf[tid]; ss[tid] = 0.f; }
    }
    __syncthreads();

    int lane = tid & 31;
    int warp = tid >> 5;
    int head = lane >> 4;
    int jj = lane & 15;
    int l4 = jj * 4;
    bool isj = jj < 8;

    float bns0 = 0.f, bns1 = 0.f, bns2 = 0.f, bns3 = 0.f;
    float bq0 = 0.f, bq1 = 0.f, bq2 = 0.f, bq3 = 0.f;

    int nwarps = gridDim.x * (blockDim.x >> 5);
    for (int nn = blockIdx.x * (blockDim.x >> 5) + warp; nn < n; nn += nwarps) {
        const float* bq_ = g_q + (size_t)nn * 256;
        float4 q4 = *(const float4*)(bq_ + lane * 4);
        float u = isj ? bq_[192 + head * 8 + jj] : 0.f;
        float qb = bq_[208 + head];
        int off0 = g_off[nn], off1 = g_off[nn + 1];

        float4 vacc = make_float4(0.f, 0.f, 0.f, 0.f);
        float den = 0.f, t = 0.f;

        int idx = off0;
        for (; idx + 2 <= off1; idx += 2) {
            int s0 = g_srcs[idx];
            int s1 = g_srcs[idx + 1];
            float ea0 = isj ? g_eatp[(size_t)idx * 8 + jj] : 0.f;
            float ea1 = isj ? g_eatp[(size_t)idx * 8 + 8 + jj] : 0.f;
            uint4 w0 = *(const uint4*)(g_kvh + (size_t)s0 * 128 + lane * 4);
            uint4 w1 = *(const uint4*)(g_kvh + (size_t)s1 * 128 + lane * 4);
            float p0 = q4.x * bflo(w0.x) + q4.y * bfhi(w0.x)
                     + q4.z * bflo(w0.z) + q4.w * bfhi(w0.z) + ea0 * u;
            float p1 = q4.x * bflo(w1.x) + q4.y * bfhi(w1.x)
                     + q4.z * bflo(w1.z) + q4.w * bfhi(w1.z) + ea1 * u;
            ull pp = pack2(p0, p1);
            pp = add2(pp, __shfl_xor_sync(0xffffffffu, pp, 8));
            pp = add2(pp, __shfl_xor_sync(0xffffffffu, pp, 4));
            pp = add2(pp, __shfl_xor_sync(0xffffffffu, pp, 2));
            pp = add2(pp, __shfl_xor_sync(0xffffffffu, pp, 1));
            float2 pr = unpack2(pp);
            float a0 = __expf(pr.x + qb);
            float a1 = __expf(pr.y + qb);
            vacc.x += a0 * bflo(w0.y) + a1 * bflo(w1.y);
            vacc.y += a0 * bfhi(w0.y) + a1 * bfhi(w1.y);
            vacc.z += a0 * bflo(w0.w) + a1 * bflo(w1.w);
            vacc.w += a0 * bfhi(w0.w) + a1 * bfhi(w1.w);
            den += a0 + a1;
            t += a0 * ea0 + a1 * ea1;
        }
        if (idx < off1) {
            int s0 = g_srcs[idx];
            float ea0 = isj ? g_eatp[(size_t)idx * 8 + jj] : 0.f;
            uint4 w0 = *(const uint4*)(g_kvh + (size_t)s0 * 128 + lane * 4);
            float p0 = q4.x * bflo(w0.x) + q4.y * bfhi(w0.x)
                     + q4.z * bflo(w0.z) + q4.w * bfhi(w0.z) + ea0 * u;
            p0 += __shfl_xor_sync(0xffffffffu, p0, 8);
            p0 += __shfl_xor_sync(0xffffffffu, p0, 4);
            p0 += __shfl_xor_sync(0xffffffffu, p0, 2);
            p0 += __shfl_xor_sync(0xffffffffu, p0, 1);
            float a0 = __expf(p0 + qb);
            vacc.x += a0 * bflo(w0.y);
            vacc.y += a0 * bfhi(w0.y);
            vacc.z += a0 * bflo(w0.w);
            vacc.w += a0 * bfhi(w0.w);
            den += a0;
            t += a0 * ea0;
        }

        float4 ep;
        ep.x = den * bfs[head * 64 + l4 + 0];
        ep.y = den * bfs[head * 64 + l4 + 1];
        ep.z = den * bfs[head * 64 + l4 + 2];
        ep.w = den * bfs[head * 64 + l4 + 3];
        #pragma unroll
        for (int j = 0; j < 8; j++) {
            float tj = __shfl_sync(0xffffffffu, t, (head << 4) + j);
            float4 w = *(float4*)&Wfs[j * 128 + head * 64 + l4];
            ep.x += tj * w.x; ep.y += tj * w.y; ep.z += tj * w.z; ep.w += tj * w.w;
        }
        float inv = (den > 0.f) ? 0.5f / den : 0.f;
        float4 agg = make_float4((vacc.x + ep.x) * inv, (vacc.y + ep.y) * inv,
                                 (vacc.z + ep.z) * inv, (vacc.w + ep.w) * inv);
        ull axy = pack2(agg.x, agg.y);
        ull azw = pack2(agg.z, agg.w);
        axy = add2(axy, __shfl_xor_sync(0xffffffffu, axy, 16));
        azw = add2(azw, __shfl_xor_sync(0xffffffffu, azw, 16));
        float2 rxy = unpack2(axy);
        float2 rzw = unpack2(azw);

        if (lane < 16) {
            float4 skip = *(const float4*)(bq_ + 128 + l4);
            float4 o = make_float4(rxy.x + skip.x, rxy.y + skip.y,
                                   rzw.x + skip.z, rzw.y + skip.w);
            *(float4*)&g_outp[(size_t)nn * 64 + l4] = o;
            bns0 += o.x; bns1 += o.y; bns2 += o.z; bns3 += o.w;
            bq0 += o.x * o.x; bq1 += o.y * o.y; bq2 += o.z * o.z; bq3 += o.w * o.w;
        }
    }

    if (lane < 16) {
        atomicAdd(&ss[l4 + 0], bns0);
        atomicAdd(&ss[l4 + 1], bns1);
        atomicAdd(&ss[l4 + 2], bns2);
        atomicAdd(&ss[l4 + 3], bns3);
        atomicAdd(&ss[64 + l4 + 0], bq0);
        atomicAdd(&ss[64 + l4 + 1], bq1);
        atomicAdd(&ss[64 + l4 + 2], bq2);
        atomicAdd(&ss[64 + l4 + 3], bq3);
    }
    __syncthreads();
    if (tid < 128) atomicAdd(&g_stats[tid], ss[tid]);
}

// ---------------- BN params ----------------
__global__ void bnparam_kernel(float invn, int zero_pool) {
    int t = threadIdx.x;  // 64
    float s = g_stats[t], sq = g_stats[64 + t];
    float mu = s * invn;
    float var = sq * invn - mu * mu;
    g_bn[t] = mu;
    g_bn[64 + t] = rsqrtf(var + 1e-5f);
    g_stats[t] = 0.f;
    g_stats[64 + t] = 0.f;
    if (zero_pool) {
        for (int i = t; i < BG * 64; i += 64) g_pool[i] = 0.f;
        if (t < BG) g_gden[t] = 0.f;
    }
}

// ---------------- pooling with fused BN-apply + leaky_relu + residual ----------------
__global__ void __launch_bounds__(256) pool_kernel(const int* __restrict__ batch,
                                                   const float* __restrict__ gate_W,
                                                   const float* __restrict__ gate_b,
                                                   const float* __restrict__ gamma,
                                                   const float* __restrict__ beta, int n) {
    for (int i = blockIdx.x * blockDim.x + threadIdx.x; i < n;
         i += gridDim.x * blockDim.x) {
        g_deg[i] = 0;
        g_cur[i] = 0;
    }

    int lane = threadIdx.x & 31;
    int w = (blockIdx.x * 256 + threadIdx.x) >> 5;
    int n0 = w * 64;
    if (n0 >= n) return;
    int n1 = min(n0 + 64, n);

    int c0 = lane * 2;
    float2 gw = ((const float2*)gate_W)[lane];
    float gb = gate_b[0];
    float2 ga = make_float2(__ldg(&gamma[c0]), __ldg(&gamma[c0 + 1]));
    float2 be = make_float2(__ldg(&beta[c0]), __ldg(&beta[c0 + 1]));
    float2 mu = make_float2(g_bn[c0], g_bn[c0 + 1]);
    float2 rs = make_float2(g_bn[64 + c0], g_bn[64 + c0 + 1]);

    int cur = -1;
    float ax = 0.f, ay = 0.f, ws = 0.f;
    for (int nn = n0; nn < n1; nn++) {
        float2 hv = ((const float2*)g_h)[nn * 32 + lane];
        float2 ov = ((const float2*)g_outp)[nn * 32 + lane];
        float v0 = ga.x * (ov.x - mu.x) * rs.x + be.x;
        float v1 = ga.y * (ov.y - mu.y) * rs.y + be.y;
        v0 = (v0 > 0.f) ? v0 : 0.01f * v0;
        v1 = (v1 > 0.f) ? v1 : 0.01f * v1;
        float h0 = hv.x + v0;
        float h1 = hv.y + v1;
        float p = h0 * gw.x + h1 * gw.y;
        p += __shfl_xor_sync(0xffffffffu, p, 16);
        p += __shfl_xor_sync(0xffffffffu, p, 8);
        p += __shfl_xor_sync(0xffffffffu, p, 4);
        p += __shfl_xor_sync(0xffffffffu, p, 2);
        p += __shfl_xor_sync(0xffffffffu, p, 1);
        float wt = __expf(p + gb);
        int b = batch[nn];
        if (b != cur) {
            if (cur >= 0) {
                atomicAdd(&g_pool[cur * 64 + c0], ax);
                atomicAdd(&g_pool[cur * 64 + c0 + 1], ay);
                if (lane == 0) atomicAdd(&g_gden[cur], ws);
            }
            cur = b; ax = ay = ws = 0.f;
        }
        ax += wt * h0;
        ay += wt * h1;
        ws += wt;
    }
    if (cur >= 0) {
        atomicAdd(&g_pool[cur * 64 + c0], ax);
        atomicAdd(&g_pool[cur * 64 + c0 + 1], ay);
        if (lane == 0) atomicAdd(&g_gden[cur], ws);
    }
}

// ---------------- final readout ----------------
__global__ void final_kernel(const float* __restrict__ out_W,
                             const float* __restrict__ out_b, float* __restrict__ out) {
    int lane = threadIdx.x & 31;
    int b = (blockIdx.x * blockDim.x + threadIdx.x) >> 5;
    if (b >= BG) return;
    float2 ow = ((const float2*)out_W)[lane];
    float2 p = ((const float2*)g_pool)[b * 32 + lane];
    float gd = g_gden[b];
    float inv = (gd > 0.f) ? 1.f / gd : 0.f;
    float v = (p.x * ow.x + p.y * ow.y) * inv;
    v += __shfl_xor_sync(0xffffffffu, v, 16);
    v += __shfl_xor_sync(0xffffffffu, v, 8);
    v += __shfl_xor_sync(0xffffffffu, v, 4);
    v += __shfl_xor_sync(0xffffffffu, v, 2);
    v += __shfl_xor_sync(0xffffffffu, v, 1);
    if (lane == 0) out[b] = 1.f / (1.f + __expf(-(v + out_b[0])));
}

// ---------------- launch ----------------
extern "C" void kernel_launch(void* const* d_in, const int* in_sizes, int n_in,
                              void* d_out, int out_size) {
    const float* x      = (const float*)d_in[0];
    const float* eat    = (const float*)d_in[1];
    const int*   esrc   = (const int*)d_in[2];
    const int*   edst   = (const int*)d_in[3];
    const int*   batch  = (const int*)d_in[4];
    const float* node_W = (const float*)d_in[5];
    const float* node_b = (const float*)d_in[6];
    const float* edge_W = (const float*)d_in[7];
    const float* edge_b = (const float*)d_in[8];
    const float* Wq     = (const float*)d_in[9];
    const float* bq     = (const float*)d_in[10];
    const float* Wk     = (const float*)d_in[11];
    const float* bk     = (const float*)d_in[12];
    const float* Wv     = (const float*)d_in[13];
    const float* bv     = (const float*)d_in[14];
    const float* We     = (const float*)d_in[15];
    const float* be     = (const float*)d_in[16];
    const float* Wskip  = (const float*)d_in[17];
    const float* bskip  = (const float*)d_in[18];
    const float* gamma  = (const float*)d_in[19];
    const float* beta   = (const float*)d_in[20];
    const float* gate_W = (const float*)d_in[21];
    const float* gate_b = (const float*)d_in[22];
    const float* out_W  = (const float*)d_in[23];
    const float* out_b  = (const float*)d_in[24];
    float* out = (float*)d_out;

    int n = in_sizes[0] / 16;
    int E = in_sizes[1] / 8;
    int nb = (n + 255) / 256;
    int nbe = (n * 64 + 255) / 256;
    int nbh = (E + 255) / 256;
    int ns2b = (2 * 64 * 18 + 2 * 18 + 255) / 256;
    int qkvs_blocks = (n + 31) / 32;
    float invn = 1.0f / (float)n;

    enc_setup1_hist_kernel<<<nbe + 128 + nbh, 256>>>(
        x, node_W, node_b, Wq, bq, Wk, bk, Wv, bv, Wskip, bskip,
        edge_W, edge_b, We, be, edst, n, E, nbe, nbh);                         // 0
    setup2_scan1_kernel<<<ns2b + nb, 256>>>(n, ns2b);                          // 1
    setup3_scan2_kernel<<<65, 256>>>(nb, n, E);                                // 2
    qkvs_kernel<<<qkvs_blocks, 256>>>(0, n, 0, gamma, beta);                   // 3 (profiled)
    scan3_kernel<<<nb, 256>>>(n);                                              // 4
    csr_scatter_kernel<<<(E + 255) / 256, 256>>>(eat, esrc, edst, E);          // 5

    gather_kernel<<<1480, 256>>>(0, n);                                        // 6
    bnparam_kernel<<<1, 64>>>(invn, 0);                                        // 7
    qkvs_kernel<<<qkvs_blocks, 256>>>(1, n, 1, gamma, beta);                   // 8
    gather_kernel<<<1480, 256>>>(1, n);                                        // 9
    bnparam_kernel<<<1, 64>>>(invn, 1);                                        // 10

    int pool_blocks = ((n + 63) / 64 + 7) / 8;
    pool_kernel<<<pool_blocks, 256>>>(batch, gate_W, gate_b,
                                      gamma + 64, beta + 64, n);               // 11
    final_kernel<<<(BG * 64 + 63) / 64, 64>>>(out_W, out_b, out);              // 12
}